// round 11
// baseline (speedup 1.0000x reference)
#include <cuda_runtime.h>
#include <cstdint>

// FuzzyNeuron via mma.sync tf32 (3xTF32 for logw, 1x tf32 for z).
// R11: occupancy attack. 1 m-tile (16 rows) per warp -> ~70 regs ->
// 6 CTAs/SM (24 warps) vs R10's 4 CTAs (16 warps, occ 19%). Persistent
// grid = 888 (one full wave), grid-stride over 2048 64-row tiles.
// Work per row unchanged; only B LDS per row doubles (L1 was 27.7%).

typedef unsigned int u32;

#define LOG2E 1.4426950408889634f
#define BLOCK 128      // 4 warps x 16 rows = 64 rows/tile
#define PL 68          // sBl float2 row stride: 2*68 % 32 == 8 -> conflict-free
#define PZ 72          // sBz float  row stride:   72 % 32 == 8 -> conflict-free
#define GRID 888       // 6 CTAs/SM x 148 SMs
#define NTILES 2048    // 131072 / 64

__device__ __forceinline__ u32 tf32_bits(float v) {
    u32 r; asm("cvt.rna.tf32.f32 %0, %1;" : "=r"(r) : "f"(v)); return r;
}
__device__ __forceinline__ float exp2_fast(float v) {
    float r; asm("ex2.approx.ftz.f32 %0, %1;" : "=f"(r) : "f"(v)); return r;
}
__device__ __forceinline__ void mma8(float* c, const u32* a, u32 b0, u32 b1) {
    asm volatile(
        "mma.sync.aligned.m16n8k8.row.col.f32.tf32.tf32.f32 "
        "{%0,%1,%2,%3}, {%4,%5,%6,%7}, {%8,%9}, {%0,%1,%2,%3};"
        : "+f"(c[0]), "+f"(c[1]), "+f"(c[2]), "+f"(c[3])
        : "r"(a[0]), "r"(a[1]), "r"(a[2]), "r"(a[3]), "r"(b0), "r"(b1));
}

__global__ void __launch_bounds__(BLOCK, 6)
fuzzy_mma_kernel(const float* __restrict__ x,
                 const float* __restrict__ mu,
                 const float* __restrict__ sigma,
                 const float* __restrict__ rho,
                 float* __restrict__ out) {
    __shared__ float2 sBl[32 * PL];               // logw B {tf32 hi, lo}
    __shared__ float  sBz[16 * PZ];               // z B (tf32 hi only)
    __shared__ __align__(16) float2 sFB[64];      // {f*log2e, bias}

    const int tid = threadIdx.x;
    const int w = tid >> 5, lane = tid & 31;
    const int g = lane >> 2, tig = lane & 3;

    // ---- build B in smem once per CTA ----
    for (int i = tid; i < 1024; i += BLOCK) {
        int kk = i & 15, n = i >> 4;
        float m = mu[i], s = sigma[i];
        float c = __fdividef(0.5f, s * s);
        float bt = 2.0f * c * m * LOG2E;
        float qt = -c * LOG2E;
        u32 bh = tf32_bits(bt);
        u32 qh = tf32_bits(qt);
        sBl[kk * PL + n] = make_float2(__uint_as_float(bh), bt - __uint_as_float(bh));
        sBl[(kk + 16) * PL + n] = make_float2(__uint_as_float(qh), qt - __uint_as_float(qh));
        sBz[kk * PZ + n] = __uint_as_float(tf32_bits(rho[n * 17 + kk]));
    }
    if (tid < 64) {
        float f = 0.0f;
        for (int a = 0; a < 16; a++) {
            float m = mu[tid * 16 + a], s = sigma[tid * 16 + a];
            f -= m * m * __fdividef(0.5f, s * s);
        }
        sFB[tid] = make_float2(f * LOG2E, rho[tid * 17 + 16]);
    }
    __syncthreads();

    // ---- persistent loop over 64-row tiles ----
    for (int t = blockIdx.x; t < NTILES; t += GRID) {
        const int rowBase = t * 64 + w * 16;

        // A fragments: rows {g, g+8}; k-cols tig+4e. 1 m-tile.
        u32 ah[4][4], al[4][4];
#pragma unroll
        for (int rh = 0; rh < 2; rh++) {
            const float* xr = x + (size_t)(rowBase + rh * 8 + g) * 16 + tig;
#pragma unroll
            for (int e = 0; e < 4; e++) {
                float v = xr[4 * e];
                u32 vh = tf32_bits(v);
                u32 vl = tf32_bits(v - __uint_as_float(vh));
                float v2 = v * v;
                u32 v2h = tf32_bits(v2);
                u32 v2l = tf32_bits(v2 - __uint_as_float(v2h));
                int ks = e >> 1;
                int slot = (e & 1) * 2 + rh;
                ah[ks][slot] = vh;      al[ks][slot] = vl;
                ah[2 + ks][slot] = v2h; al[2 + ks][slot] = v2l;
            }
        }

        float num0 = 0.f, num1 = 0.f, den0 = 0.f, den1 = 0.f;

        // 8 rule chunks of 8 rules; 3-way-split logw accumulators
        for (int j = 0; j < 8; j++) {
            float c1[4] = {0.f, 0.f, 0.f, 0.f};   // Ahi*Bhi
            float c2[4] = {0.f, 0.f, 0.f, 0.f};   // Alo*Bhi
            float c3[4] = {0.f, 0.f, 0.f, 0.f};   // Ahi*Blo
            float cz[4] = {0.f, 0.f, 0.f, 0.f};
#pragma unroll
            for (int ks = 0; ks < 4; ks++) {
                float2 Bl0 = sBl[(ks * 8 + tig) * PL + j * 8 + g];
                float2 Bl1 = sBl[(ks * 8 + tig + 4) * PL + j * 8 + g];
                mma8(c1, ah[ks], __float_as_uint(Bl0.x), __float_as_uint(Bl1.x));
                mma8(c2, al[ks], __float_as_uint(Bl0.x), __float_as_uint(Bl1.x));
                mma8(c3, ah[ks], __float_as_uint(Bl0.y), __float_as_uint(Bl1.y));
            }
#pragma unroll
            for (int ks = 0; ks < 2; ks++) {      // z: K=16, hi only
                u32 bz0 = __float_as_uint(sBz[(ks * 8 + tig) * PZ + j * 8 + g]);
                u32 bz1 = __float_as_uint(sBz[(ks * 8 + tig + 4) * PZ + j * 8 + g]);
                mma8(cz, ah[ks], bz0, bz1);
            }
            // epilogue for rules 8j+2tig, 8j+2tig+1
            float4 q = *reinterpret_cast<const float4*>(&sFB[8 * j + 2 * tig]); // {f0,b0,f1,b1}
            float w00 = exp2_fast(c1[0] + c2[0] + c3[0] + q.x);
            float w01 = exp2_fast(c1[1] + c2[1] + c3[1] + q.z);
            float w10 = exp2_fast(c1[2] + c2[2] + c3[2] + q.x);
            float w11 = exp2_fast(c1[3] + c2[3] + c3[3] + q.z);
            num0 = fmaf(cz[0] + q.y, w00, num0);
            num0 = fmaf(cz[1] + q.w, w01, num0);
            num1 = fmaf(cz[2] + q.y, w10, num1);
            num1 = fmaf(cz[3] + q.w, w11, num1);
            den0 += w00 + w01;
            den1 += w10 + w11;
        }

        // reduce across 4 tig lanes; tig==0 writes rows rowBase+g, rowBase+8+g
        num0 += __shfl_xor_sync(0xffffffffu, num0, 1);
        den0 += __shfl_xor_sync(0xffffffffu, den0, 1);
        num0 += __shfl_xor_sync(0xffffffffu, num0, 2);
        den0 += __shfl_xor_sync(0xffffffffu, den0, 2);
        num1 += __shfl_xor_sync(0xffffffffu, num1, 1);
        den1 += __shfl_xor_sync(0xffffffffu, den1, 1);
        num1 += __shfl_xor_sync(0xffffffffu, num1, 2);
        den1 += __shfl_xor_sync(0xffffffffu, den1, 2);
        if (tig == 0) {
            out[rowBase + g] = num0 / (den0 + 1e-13f);
            out[rowBase + 8 + g] = num1 / (den1 + 1e-13f);
        }
    }
}

extern "C" void kernel_launch(void* const* d_in, const int* in_sizes, int n_in,
                              void* d_out, int out_size) {
    const float* x = (const float*)d_in[0];      // [N, 16]
    const float* mu = (const float*)d_in[1];     // [64, 16]
    const float* sigma = (const float*)d_in[2];  // [64, 16]
    const float* rho = (const float*)d_in[3];    // [64, 17]
    float* out = (float*)d_out;                  // [N]

    fuzzy_mma_kernel<<<GRID, BLOCK>>>(x, mu, sigma, rho, out);
}